// round 11
// baseline (speedup 1.0000x reference)
#include <cuda_runtime.h>
#include <cuda_bf16.h>

#define T_STEPS  1024
#define F_FEAT   2048
#define LATENT   128
#define ODE_H    256
#define GR       384          // 3*LATENT gate rows
#define G        16           // features per CTA
#define GPG      2            // feature pairs per group
#define NGRP     4
#define NTHREADS 512
#define NCTAS    (F_FEAT / G) // 128

typedef unsigned long long u64;

// ---------- packed f32x2 helpers ----------
__device__ __forceinline__ u64 ffma2(u64 a, u64 b, u64 c) {
    u64 d;
    asm("fma.rn.f32x2 %0, %1, %2, %3;" : "=l"(d) : "l"(a), "l"(b), "l"(c));
    return d;
}
__device__ __forceinline__ float2 unpk(u64 v) {
    float2 r;
    asm("mov.b64 {%0, %1}, %2;" : "=f"(r.x), "=f"(r.y) : "l"(v));
    return r;
}
__device__ __forceinline__ u64 pack2(float x, float y) {
    u64 r;
    asm("mov.b64 %0, {%1, %2};" : "=l"(r) : "f"(x), "f"(y));
    return r;
}
__device__ __forceinline__ u64 dupbits(unsigned int x) {
    u64 r;
    asm("mov.b64 %0, {%1, %1};" : "=l"(r) : "r"(x));
    return r;
}
// expand 4 bf16 weights (uint2) into 4 broadcast f32x2 operands
__device__ __forceinline__ void expand4(uint2 w, u64& w0, u64& w1, u64& w2, u64& w3) {
    const unsigned int a = w.x << 16;
    const unsigned int b = w.x & 0xFFFF0000u;
    const unsigned int c = w.y << 16;
    const unsigned int d = w.y & 0xFFFF0000u;
    w0 = dupbits(a); w1 = dupbits(b); w2 = dupbits(c); w3 = dupbits(d);
}
__device__ __forceinline__ float tanh_fast(float x) {
    float y;
    asm("tanh.approx.f32 %0, %1;" : "=f"(y) : "f"(x));
    return y;
}
__device__ __forceinline__ u64 tanh2(u64 v) {
    const float2 f = unpk(v);
    return pack2(tanh_fast(f.x), tanh_fast(f.y));
}
__device__ __forceinline__ float fast_sigmoid(float x) {
    return fmaf(0.5f, tanh_fast(0.5f * x), 0.5f);
}
#define GBAR(id) asm volatile("bar.sync %0, 128;" :: "r"(id) : "memory")

// ---------- repacked bf16 weights (transposed, ~224 KB total) ----------
__device__ uint2 g_W1h[32 * 256];
__device__ uint2 g_W2h[64 * 128];
__device__ uint2 g_Whh[32 * 384];

__device__ __forceinline__ uint2 to_bf16x4(const float* src) {
    __nv_bfloat162 lo = __floats2bfloat162_rn(src[0], src[1]);
    __nv_bfloat162 hi = __floats2bfloat162_rn(src[2], src[3]);
    uint2 r;
    r.x = *(unsigned int*)&lo;
    r.y = *(unsigned int*)&hi;
    return r;
}

__global__ void repack_kernel(const float* __restrict__ W1,
                              const float* __restrict__ W2,
                              const float* __restrict__ Whh)
{
    int i = blockIdx.x * blockDim.x + threadIdx.x;
    if (i < 32 * 256) {
        int k4 = i >> 8, j = i & 255;
        g_W1h[k4 * 256 + j] = to_bf16x4(W1 + j * LATENT + 4 * k4);
    } else if (i < 32 * 256 + 64 * 128) {
        int t = i - 32 * 256;
        int k4 = t >> 7, j = t & 127;
        g_W2h[k4 * 128 + j] = to_bf16x4(W2 + j * ODE_H + 4 * k4);
    } else if (i < 32 * 256 + 64 * 128 + 32 * 384) {
        int t = i - (32 * 256 + 64 * 128);
        int k4 = t / 384, j = t % 384;
        g_Whh[k4 * 384 + j] = to_bf16x4(Whh + j * LATENT + 4 * k4);
    }
}

// ---------- main persistent recurrence kernel ----------
__global__ __launch_bounds__(NTHREADS, 1)
void ode_rnn_kernel(const float* __restrict__ times,
                    const float* __restrict__ vals,
                    const float* __restrict__ mask,
                    const float* __restrict__ b1,
                    const float* __restrict__ b2,
                    const float* __restrict__ W_ih,
                    const float* __restrict__ b_ih,
                    const float* __restrict__ b_hh,
                    float* __restrict__ out)
{
    // 4 independent groups; each owns 2 feature-pairs (f32x2 across features)
    __shared__ __align__(16) u64 hp[NGRP * GPG * LATENT];   // 8 KB
    __shared__ __align__(16) u64 pool[NGRP * GPG * GR];     // 24 KB
    __shared__ float2 obs2[NGRP * GPG];
    __shared__ float2 m2[NGRP * GPG];

    const int tid = threadIdx.x;
    const int grp = tid >> 7;              // 0..3
    const int lt  = tid & 127;             // lane within group
    const int bar = grp + 1;               // named barrier id
    const int f0  = blockIdx.x * G;
    u64* __restrict__ hpg   = hp   + grp * GPG * LATENT;
    u64* __restrict__ poolg = pool + grp * GPG * GR;
    const int pb = grp * GPG;              // global pair base

    // loop-invariant per-thread bias/weight preloads
    const float b1j0v = __ldg(b1 + lt);
    const float b1j1v = __ldg(b1 + lt + 128);
    const float b2jv  = __ldg(b2 + lt);
    const float bh0v  = __ldg(b_hh + lt);
    const float bh1v  = __ldg(b_hh + lt + 128);
    const float bh2v  = __ldg(b_hh + lt + 256);
    const float wr = __ldg(W_ih + lt);
    const float wz = __ldg(W_ih + LATENT + lt);
    const float wn = __ldg(W_ih + 2 * LATENT + lt);
    const float br = __ldg(b_ih + lt);
    const float bz = __ldg(b_ih + LATENT + lt);
    const float bn = __ldg(b_ih + 2 * LATENT + lt);

    for (int idx = tid; idx < NGRP * GPG * LATENT; idx += NTHREADS)
        hp[idx] = 0ULL;
    __syncthreads();

    for (int i = 0; i < T_STEPS; ++i) {
        const int row = T_STEPS - 1 - i;               // reversed sequence
        float dt = 0.0f;
        if (i > 0) dt = __ldg(times + row + 1) - __ldg(times + row);

        if (lt < GPG) {
            obs2[pb + lt] = __ldg((const float2*)(vals + (long)row * F_FEAT + f0) + pb + lt);
            m2[pb + lt]   = __ldg((const float2*)(mask + (long)row * F_FEAT + f0) + pb + lt);
        }

        if (dt > 0.0f) {
            // ---- Phase 1: t1[p][j] = tanh(b1[j] + sum_k h2[p][k]*W1[j][k])
            //      JR=2 (rows lt, lt+128), 2 pairs ----
            {
                const int j0 = lt, j1 = lt + 128;
                u64 a0[GPG], a1[GPG];
                const u64 bj0 = pack2(b1j0v, b1j0v);
                const u64 bj1 = pack2(b1j1v, b1j1v);
                #pragma unroll
                for (int p = 0; p < GPG; ++p) { a0[p] = bj0; a1[p] = bj1; }
                #pragma unroll 4
                for (int k4 = 0; k4 < LATENT / 4; ++k4) {
                    const uint2 ra = __ldg(g_W1h + k4 * ODE_H + j0);
                    const uint2 rb = __ldg(g_W1h + k4 * ODE_H + j1);
                    u64 wa0, wa1, wa2, wa3, wb0, wb1, wb2, wb3;
                    expand4(ra, wa0, wa1, wa2, wa3);
                    expand4(rb, wb0, wb1, wb2, wb3);
                    #pragma unroll
                    for (int p = 0; p < GPG; ++p) {
                        const ulonglong2* hv = (const ulonglong2*)(hpg + p * LATENT);
                        const ulonglong2 x = hv[2 * k4];
                        const ulonglong2 y = hv[2 * k4 + 1];
                        a0[p] = ffma2(x.x, wa0, a0[p]); a1[p] = ffma2(x.x, wb0, a1[p]);
                        a0[p] = ffma2(x.y, wa1, a0[p]); a1[p] = ffma2(x.y, wb1, a1[p]);
                        a0[p] = ffma2(y.x, wa2, a0[p]); a1[p] = ffma2(y.x, wb2, a1[p]);
                        a0[p] = ffma2(y.y, wa3, a0[p]); a1[p] = ffma2(y.y, wb3, a1[p]);
                    }
                }
                #pragma unroll
                for (int p = 0; p < GPG; ++p) {
                    poolg[p * ODE_H + j0] = tanh2(a0[p]);
                    poolg[p * ODE_H + j1] = tanh2(a1[p]);
                }
            }
            GBAR(bar);

            // ---- Phase 2: h2[p][j] += dt * (b2[j] + sum_k t1[p][k]*W2[j][k])
            //      JR=1 (row lt), 2 pairs ----
            {
                const int j = lt;
                u64 acc[GPG];
                const u64 bj = pack2(b2jv, b2jv);
                #pragma unroll
                for (int p = 0; p < GPG; ++p) acc[p] = bj;
                #pragma unroll 4
                for (int k4 = 0; k4 < ODE_H / 4; ++k4) {
                    const uint2 rw = __ldg(g_W2h + k4 * LATENT + j);
                    u64 w0, w1, w2, w3;
                    expand4(rw, w0, w1, w2, w3);
                    #pragma unroll
                    for (int p = 0; p < GPG; ++p) {
                        const ulonglong2* tv = (const ulonglong2*)(poolg + p * ODE_H);
                        const ulonglong2 x = tv[2 * k4];
                        const ulonglong2 y = tv[2 * k4 + 1];
                        acc[p] = ffma2(x.x, w0, acc[p]);
                        acc[p] = ffma2(x.y, w1, acc[p]);
                        acc[p] = ffma2(y.x, w2, acc[p]);
                        acc[p] = ffma2(y.y, w3, acc[p]);
                    }
                }
                const u64 dt2 = pack2(dt, dt);
                #pragma unroll
                for (int p = 0; p < GPG; ++p)
                    hpg[p * LATENT + j] = ffma2(acc[p], dt2, hpg[p * LATENT + j]);
            }
            GBAR(bar);
        }

        // ---- Phase 3: gh[p][j] = b_hh[j] + sum_k h2[p][k]*W_hh[j][k]
        //      JR=3 (rows lt, lt+128, lt+256), 2 pairs ----
        {
            const int j0 = lt, j1 = lt + 128, j2 = lt + 256;
            u64 a0[GPG], a1[GPG], a2[GPG];
            const u64 bj0 = pack2(bh0v, bh0v);
            const u64 bj1 = pack2(bh1v, bh1v);
            const u64 bj2 = pack2(bh2v, bh2v);
            #pragma unroll
            for (int p = 0; p < GPG; ++p) { a0[p] = bj0; a1[p] = bj1; a2[p] = bj2; }
            #pragma unroll 4
            for (int k4 = 0; k4 < LATENT / 4; ++k4) {
                const uint2 ra = __ldg(g_Whh + k4 * GR + j0);
                const uint2 rb = __ldg(g_Whh + k4 * GR + j1);
                const uint2 rc = __ldg(g_Whh + k4 * GR + j2);
                u64 wa0, wa1, wa2, wa3, wb0, wb1, wb2, wb3, wc0, wc1, wc2, wc3;
                expand4(ra, wa0, wa1, wa2, wa3);
                expand4(rb, wb0, wb1, wb2, wb3);
                expand4(rc, wc0, wc1, wc2, wc3);
                #pragma unroll
                for (int p = 0; p < GPG; ++p) {
                    const ulonglong2* hv = (const ulonglong2*)(hpg + p * LATENT);
                    const ulonglong2 x = hv[2 * k4];
                    const ulonglong2 y = hv[2 * k4 + 1];
                    a0[p] = ffma2(x.x, wa0, a0[p]); a1[p] = ffma2(x.x, wb0, a1[p]); a2[p] = ffma2(x.x, wc0, a2[p]);
                    a0[p] = ffma2(x.y, wa1, a0[p]); a1[p] = ffma2(x.y, wb1, a1[p]); a2[p] = ffma2(x.y, wc1, a2[p]);
                    a0[p] = ffma2(y.x, wa2, a0[p]); a1[p] = ffma2(y.x, wb2, a1[p]); a2[p] = ffma2(y.x, wc2, a2[p]);
                    a0[p] = ffma2(y.y, wa3, a0[p]); a1[p] = ffma2(y.y, wb3, a1[p]); a2[p] = ffma2(y.y, wc3, a2[p]);
                }
            }
            #pragma unroll
            for (int p = 0; p < GPG; ++p) {
                poolg[p * GR + j0] = a0[p];
                poolg[p * GR + j1] = a1[p];
                poolg[p * GR + j2] = a2[p];
            }
        }
        GBAR(bar);

        // ---- Update: GRU gates + mask mix (256 pair-elems per group) ----
        #pragma unroll
        for (int p = 0; p < GPG; ++p) {
            const int l = lt;
            const float2 gr = unpk(poolg[p * GR + l]);
            const float2 gz = unpk(poolg[p * GR + LATENT + l]);
            const float2 gn = unpk(poolg[p * GR + 2 * LATENT + l]);
            const float2 ob = obs2[pb + p];
            const float2 mm = m2[pb + p];
            const float2 h  = unpk(hpg[p * LATENT + l]);

            const float rX = fast_sigmoid(fmaf(ob.x, wr, br) + gr.x);
            const float zX = fast_sigmoid(fmaf(ob.x, wz, bz) + gz.x);
            const float nX = tanh_fast(fmaf(ob.x, wn, bn) + rX * gn.x);
            const float hcX = fmaf(zX, h.x - nX, nX);
            const float hX  = fmaf(mm.x, hcX - h.x, h.x);

            const float rY = fast_sigmoid(fmaf(ob.y, wr, br) + gr.y);
            const float zY = fast_sigmoid(fmaf(ob.y, wz, bz) + gz.y);
            const float nY = tanh_fast(fmaf(ob.y, wn, bn) + rY * gn.y);
            const float hcY = fmaf(zY, h.y - nY, nY);
            const float hY  = fmaf(mm.y, hcY - h.y, h.y);

            hpg[p * LATENT + l] = pack2(hX, hY);
        }
        GBAR(bar);
    }

    // write final h for this group's 2 pairs
    #pragma unroll
    for (int p = 0; p < GPG; ++p) {
        const float2 v = unpk(hpg[p * LATENT + lt]);
        out[(long)(f0 + 2 * (pb + p))     * LATENT + lt] = v.x;
        out[(long)(f0 + 2 * (pb + p) + 1) * LATENT + lt] = v.y;
    }
}

extern "C" void kernel_launch(void* const* d_in, const int* in_sizes, int n_in,
                              void* d_out, int out_size)
{
    (void)in_sizes; (void)n_in; (void)out_size;
    const float* times = (const float*)d_in[0];
    const float* vals  = (const float*)d_in[1];
    const float* mask  = (const float*)d_in[2];
    const float* W1    = (const float*)d_in[3];
    const float* b1    = (const float*)d_in[4];
    const float* W2    = (const float*)d_in[5];
    const float* b2    = (const float*)d_in[6];
    const float* W_ih  = (const float*)d_in[7];
    const float* b_ih  = (const float*)d_in[8];
    const float* W_hh  = (const float*)d_in[9];
    const float* b_hh  = (const float*)d_in[10];
    float* out = (float*)d_out;

    const int total = 32 * 256 + 64 * 128 + 32 * 384;
    repack_kernel<<<(total + 255) / 256, 256>>>(W1, W2, W_hh);
    ode_rnn_kernel<<<NCTAS, NTHREADS>>>(times, vals, mask,
                                        b1, b2, W_ih, b_ih, b_hh, out);
}

// round 13
// speedup vs baseline: 4.4001x; 4.4001x over previous
#include <cuda_runtime.h>
#include <cuda_bf16.h>
#include <cstdint>

#define T_STEPS 1024
#define F_FEAT  2048
#define MF      16
#define NCTA    (F_FEAT / MF)   // 128
#define THREADS 256

// ---- packed bf16 weight-fragment image (global, ~224 KB, L1-resident) ----
// uint4 per (tile, ktpair, lane): {b0,b1} of kt_even and kt_odd B-fragments.
#define W1_BASE 0       // W1  (256x128): nt<32, ktp<4  -> 4096 uint4
#define W2_BASE 4096    // W2  (128x256): nt<16, ktp<8  -> 4096
#define WH_BASE 8192    // Whh (384x128): nt<48, ktp<4  -> 6144
__device__ __align__(16) uint4 g_Wfrag[14336];

__device__ __forceinline__ uint32_t bfbits(__nv_bfloat162 v) {
    return *reinterpret_cast<uint32_t*>(&v);
}

__global__ void repack_kernel(const float* __restrict__ W1,
                              const float* __restrict__ W2,
                              const float* __restrict__ Whh)
{
    int i = blockIdx.x * blockDim.x + threadIdx.x;
    if (i >= 14336) return;
    const float* W; int NK, r;
    if (i < 4096)      { W = W1;  NK = 128; r = i; }
    else if (i < 8192) { W = W2;  NK = 256; r = i - 4096; }
    else               { W = Whh; NK = 128; r = i - 8192; }
    const int NKTP = NK / 32;
    const int nt   = r / (NKTP * 32);
    const int ktp  = (r / 32) % NKTP;
    const int lane = r & 31;
    const int j  = nt * 8 + (lane >> 2);          // output row (B col)
    const int k0 = ktp * 32 + (lane & 3) * 2;     // k of kt_even, this lane
    const float* row = W + (long)j * NK;
    uint4 v;
    v.x = bfbits(__floats2bfloat162_rn(row[k0],      row[k0 + 1]));
    v.y = bfbits(__floats2bfloat162_rn(row[k0 + 8],  row[k0 + 9]));
    v.z = bfbits(__floats2bfloat162_rn(row[k0 + 16], row[k0 + 17]));
    v.w = bfbits(__floats2bfloat162_rn(row[k0 + 24], row[k0 + 25]));
    g_Wfrag[i] = v;
}

// ---- helpers ----
__device__ __forceinline__ void mma4(float* c, const uint4& a, uint32_t b0, uint32_t b1) {
    asm volatile("mma.sync.aligned.m16n8k16.row.col.f32.bf16.bf16.f32 "
        "{%0,%1,%2,%3}, {%4,%5,%6,%7}, {%8,%9}, {%0,%1,%2,%3};"
        : "+f"(c[0]), "+f"(c[1]), "+f"(c[2]), "+f"(c[3])
        : "r"(a.x), "r"(a.y), "r"(a.z), "r"(a.w), "r"(b0), "r"(b1));
}
__device__ __forceinline__ float tanh_fast(float x) {
    float y; asm("tanh.approx.f32 %0, %1;" : "=f"(y) : "f"(x)); return y;
}
__device__ __forceinline__ float fsig(float x) {
    return fmaf(0.5f, tanh_fast(0.5f * x), 0.5f);
}
// pack {low=ev, high=od} bf16x2
__device__ __forceinline__ uint32_t packbf(float ev, float od) {
    uint32_t d; asm("cvt.rn.bf16x2.f32 %0, %1, %2;" : "=r"(d) : "f"(od), "f"(ev)); return d;
}
__device__ __forceinline__ float lo16f(uint32_t u) { return __uint_as_float(u << 16); }
__device__ __forceinline__ float hi16f(uint32_t u) { return __uint_as_float(u & 0xFFFF0000u); }

// split 8 fp32 (A-frag order) into hi/lo bf16 A-frags
__device__ __forceinline__ void split_frag(const float* v, uint4& hi, uint4& lo) {
    hi.x = packbf(v[0], v[1]); lo.x = packbf(v[0] - lo16f(hi.x), v[1] - hi16f(hi.x));
    hi.y = packbf(v[2], v[3]); lo.y = packbf(v[2] - lo16f(hi.y), v[3] - hi16f(hi.y));
    hi.z = packbf(v[4], v[5]); lo.z = packbf(v[4] - lo16f(hi.z), v[5] - hi16f(hi.z));
    hi.w = packbf(v[6], v[7]); lo.w = packbf(v[6] - lo16f(hi.w), v[7] - hi16f(hi.w));
}

// ---- main kernel ----
__global__ void __launch_bounds__(THREADS, 1)
ode_mma_kernel(const float* __restrict__ times, const float* __restrict__ vals,
               const float* __restrict__ mask,  const float* __restrict__ b1,
               const float* __restrict__ b2,    const float* __restrict__ W_ih,
               const float* __restrict__ b_ih,  const float* __restrict__ b_hh,
               float* __restrict__ out)
{
    // A-fragment stores: [kt][half(hi/lo)][lane]
    __shared__ __align__(16) uint4 hfrag[8 * 2 * 32];     // h  (K=128)  8 KB
    __shared__ __align__(16) uint4 t1frag[16 * 2 * 32];   // T1 (K=256) 16 KB
    __shared__ float obs_s[16], m_s[16];

    const int tid = threadIdx.x, w = tid >> 5, lane = tid & 31;
    const int g = lane >> 2, t = lane & 3;
    const int f0 = blockIdx.x * MF;

    // ---- loop-invariant per-lane preloads ----
    float b1v[8];
    #pragma unroll
    for (int nt = 0; nt < 4; ++nt) {
        const int j = 32 * w + nt * 8 + 2 * t;
        b1v[nt * 2]     = __ldg(b1 + j);
        b1v[nt * 2 + 1] = __ldg(b1 + j + 1);
    }
    float b2v[8], bcr[8], bcz[8], bhn[8], bin[8], wir[8], wiz[8], win[8];
    #pragma unroll
    for (int q = 0; q < 8; ++q) {
        const int k = 16 * w + (q >> 2) * 8 + 2 * t + (q & 1);
        b2v[q] = __ldg(b2 + k);
        bcr[q] = __ldg(b_hh + k)       + __ldg(b_ih + k);
        bcz[q] = __ldg(b_hh + 128 + k) + __ldg(b_ih + 128 + k);
        bhn[q] = __ldg(b_hh + 256 + k);
        bin[q] = __ldg(b_ih + 256 + k);
        wir[q] = __ldg(W_ih + k);
        wiz[q] = __ldg(W_ih + 128 + k);
        win[q] = __ldg(W_ih + 256 + k);
    }

    // h master: 8 fp32/lane, A-frag order {a0.xy, a1.xy, a2.xy, a3.xy}
    // rows {g, g, g+8, g+8, g, g, g+8, g+8}; k = 16w + (q>>2)*8 + 2t + (q&1)
    float h[8];
    #pragma unroll
    for (int q = 0; q < 8; ++q) h[q] = 0.0f;

    {   // init h frag (ktile w)
        uint4 hi, lo;
        split_frag(h, hi, lo);
        hfrag[(w * 2 + 0) * 32 + lane] = hi;
        hfrag[(w * 2 + 1) * 32 + lane] = lo;
    }
    __syncthreads();

    for (int i = 0; i < T_STEPS; ++i) {
        const int rowi = T_STEPS - 1 - i;              // reversed sequence
        float dt = 0.0f;
        if (i > 0) dt = __ldg(times + rowi + 1) - __ldg(times + rowi);

        if (tid < 16)      obs_s[tid]    = __ldg(vals + (long)rowi * F_FEAT + f0 + tid);
        else if (tid < 32) m_s[tid - 16] = __ldg(mask + (long)rowi * F_FEAT + f0 + tid - 16);

        if (dt > 0.0f) {
            // ---- P1: C(16x256) = H(16x128) @ W1^T ; warp w: n-cols [32w,32w+32) ----
            float c[4][4];
            #pragma unroll
            for (int nt = 0; nt < 4; ++nt)
                #pragma unroll
                for (int cc = 0; cc < 4; ++cc) c[nt][cc] = 0.0f;
            #pragma unroll
            for (int ktp = 0; ktp < 4; ++ktp) {
                const uint4 ah0 = hfrag[((2 * ktp)     * 2 + 0) * 32 + lane];
                const uint4 al0 = hfrag[((2 * ktp)     * 2 + 1) * 32 + lane];
                const uint4 ah1 = hfrag[((2 * ktp + 1) * 2 + 0) * 32 + lane];
                const uint4 al1 = hfrag[((2 * ktp + 1) * 2 + 1) * 32 + lane];
                #pragma unroll
                for (int nt = 0; nt < 4; ++nt) {
                    const uint4 bw = __ldg(&g_Wfrag[W1_BASE + (((4 * w + nt) * 4 + ktp) * 32 + lane)]);
                    mma4(c[nt], ah0, bw.x, bw.y);
                    mma4(c[nt], al0, bw.x, bw.y);
                    mma4(c[nt], ah1, bw.z, bw.w);
                    mma4(c[nt], al1, bw.z, bw.w);
                }
            }
            // epilogue: tanh(+b1) -> T1 A-frags (ktiles 2w, 2w+1)
            float v[16];
            #pragma unroll
            for (int nt = 0; nt < 4; ++nt)
                #pragma unroll
                for (int cc = 0; cc < 4; ++cc)
                    v[nt * 4 + cc] = tanh_fast(c[nt][cc] + b1v[nt * 2 + (cc & 1)]);
            #pragma unroll
            for (int kt2 = 0; kt2 < 2; ++kt2) {
                uint4 hi, lo;
                split_frag(v + kt2 * 8, hi, lo);
                t1frag[((2 * w + kt2) * 2 + 0) * 32 + lane] = hi;
                t1frag[((2 * w + kt2) * 2 + 1) * 32 + lane] = lo;
            }
            __syncthreads();

            // ---- P2: C(16x128) = T1(16x256) @ W2^T ; warp w: n-cols [16w,16w+16) ----
            float d[2][4];
            #pragma unroll
            for (int nt = 0; nt < 2; ++nt)
                #pragma unroll
                for (int cc = 0; cc < 4; ++cc) d[nt][cc] = 0.0f;
            #pragma unroll
            for (int ktp = 0; ktp < 8; ++ktp) {
                const uint4 ah0 = t1frag[((2 * ktp)     * 2 + 0) * 32 + lane];
                const uint4 al0 = t1frag[((2 * ktp)     * 2 + 1) * 32 + lane];
                const uint4 ah1 = t1frag[((2 * ktp + 1) * 2 + 0) * 32 + lane];
                const uint4 al1 = t1frag[((2 * ktp + 1) * 2 + 1) * 32 + lane];
                #pragma unroll
                for (int nt = 0; nt < 2; ++nt) {
                    const uint4 bw = __ldg(&g_Wfrag[W2_BASE + (((2 * w + nt) * 8 + ktp) * 32 + lane)]);
                    mma4(d[nt], ah0, bw.x, bw.y);
                    mma4(d[nt], al0, bw.x, bw.y);
                    mma4(d[nt], ah1, bw.z, bw.w);
                    mma4(d[nt], al1, bw.z, bw.w);
                }
            }
            // epilogue: h += dt * (dH + b2); refresh h frag
            #pragma unroll
            for (int q = 0; q < 8; ++q)
                h[q] = fmaf(dt, d[q >> 2][q & 3] + b2v[q], h[q]);
            {
                uint4 hi, lo;
                split_frag(h, hi, lo);
                hfrag[(w * 2 + 0) * 32 + lane] = hi;
                hfrag[(w * 2 + 1) * 32 + lane] = lo;
            }
        }
        __syncthreads();

        // ---- P3: GH(16x384) = H @ Whh^T ; warp w: cols 16w..16w+16 in each third ----
        float e[6][4];
        #pragma unroll
        for (int nt = 0; nt < 6; ++nt)
            #pragma unroll
            for (int cc = 0; cc < 4; ++cc) e[nt][cc] = 0.0f;
        #pragma unroll
        for (int ktp = 0; ktp < 4; ++ktp) {
            const uint4 ah0 = hfrag[((2 * ktp)     * 2 + 0) * 32 + lane];
            const uint4 al0 = hfrag[((2 * ktp)     * 2 + 1) * 32 + lane];
            const uint4 ah1 = hfrag[((2 * ktp + 1) * 2 + 0) * 32 + lane];
            const uint4 al1 = hfrag[((2 * ktp + 1) * 2 + 1) * 32 + lane];
            #pragma unroll
            for (int th = 0; th < 3; ++th)
                #pragma unroll
                for (int nt = 0; nt < 2; ++nt) {
                    const uint4 bw = __ldg(&g_Wfrag[WH_BASE + (((th * 16 + 2 * w + nt) * 4 + ktp) * 32 + lane)]);
                    float* acc = e[th * 2 + nt];
                    mma4(acc, ah0, bw.x, bw.y);
                    mma4(acc, al0, bw.x, bw.y);
                    mma4(acc, ah1, bw.z, bw.w);
                    mma4(acc, al1, bw.z, bw.w);
                }
        }
        // epilogue: GRU + mask mix, in-place on h regs (C layout == h layout)
        {
            const float ob0 = obs_s[g], ob1 = obs_s[g + 8];
            const float mm0 = m_s[g],   mm1 = m_s[g + 8];
            #pragma unroll
            for (int q = 0; q < 8; ++q) {
                const int tile = q >> 2, cc = q & 3;
                const float ob = (cc & 2) ? ob1 : ob0;
                const float mm = (cc & 2) ? mm1 : mm0;
                const float r = fsig(fmaf(ob, wir[q], bcr[q]) + e[tile][cc]);
                const float z = fsig(fmaf(ob, wiz[q], bcz[q]) + e[2 + tile][cc]);
                const float n = tanh_fast(fmaf(ob, win[q], bin[q]) + r * (e[4 + tile][cc] + bhn[q]));
                const float hv = h[q];
                const float hc = fmaf(z, hv - n, n);          // (1-z)n + z h
                h[q] = fmaf(mm, hc - hv, hv);                 // m hc + (1-m) h
            }
        }
        {
            uint4 hi, lo;
            split_frag(h, hi, lo);
            hfrag[(w * 2 + 0) * 32 + lane] = hi;
            hfrag[(w * 2 + 1) * 32 + lane] = lo;
        }
        __syncthreads();
    }

    // ---- output: decode fragment layout ----
    #pragma unroll
    for (int q = 0; q < 8; ++q) {
        const int rowf = g + ((q & 3) >> 1) * 8;
        const int k    = 16 * w + (q >> 2) * 8 + 2 * t + (q & 1);
        out[(long)(f0 + rowf) * 128 + k] = h[q];
    }
}

extern "C" void kernel_launch(void* const* d_in, const int* in_sizes, int n_in,
                              void* d_out, int out_size)
{
    (void)in_sizes; (void)n_in; (void)out_size;
    const float* times = (const float*)d_in[0];
    const float* vals  = (const float*)d_in[1];
    const float* mask  = (const float*)d_in[2];
    const float* W1    = (const float*)d_in[3];
    const float* b1    = (const float*)d_in[4];
    const float* W2    = (const float*)d_in[5];
    const float* b2    = (const float*)d_in[6];
    const float* W_ih  = (const float*)d_in[7];
    const float* b_ih  = (const float*)d_in[8];
    const float* W_hh  = (const float*)d_in[9];
    const float* b_hh  = (const float*)d_in[10];
    float* out = (float*)d_out;

    repack_kernel<<<56, 256>>>(W1, W2, W_hh);
    ode_mma_kernel<<<NCTA, THREADS>>>(times, vals, mask, b1, b2,
                                      W_ih, b_ih, b_hh, out);
}

// round 14
// speedup vs baseline: 5.4241x; 1.2327x over previous
#include <cuda_runtime.h>
#include <cuda_bf16.h>
#include <cstdint>

#define T_STEPS 1024
#define F_FEAT  2048
#define MF      16
#define NCTA    (F_FEAT / MF)   // 128
#define THREADS 256

// ---- packed bf16 weight-fragment image (global, ~224 KB, L1-resident) ----
#define W1_BASE 0       // W1  (256x128): nt<32, ktp<4  -> 4096 uint4
#define W2_BASE 4096    // W2  (128x256): nt<16, ktp<8  -> 4096
#define WH_BASE 8192    // Whh (384x128): nt<48, ktp<4  -> 6144
__device__ __align__(16) uint4 g_Wfrag[14336];

__device__ __forceinline__ uint32_t bfbits(__nv_bfloat162 v) {
    return *reinterpret_cast<uint32_t*>(&v);
}

__global__ void repack_kernel(const float* __restrict__ W1,
                              const float* __restrict__ W2,
                              const float* __restrict__ Whh)
{
    int i = blockIdx.x * blockDim.x + threadIdx.x;
    if (i >= 14336) return;
    const float* W; int NK, r;
    if (i < 4096)      { W = W1;  NK = 128; r = i; }
    else if (i < 8192) { W = W2;  NK = 256; r = i - 4096; }
    else               { W = Whh; NK = 128; r = i - 8192; }
    const int NKTP = NK / 32;
    const int nt   = r / (NKTP * 32);
    const int ktp  = (r / 32) % NKTP;
    const int lane = r & 31;
    const int j  = nt * 8 + (lane >> 2);
    const int k0 = ktp * 32 + (lane & 3) * 2;
    const float* row = W + (long)j * NK;
    uint4 v;
    v.x = bfbits(__floats2bfloat162_rn(row[k0],      row[k0 + 1]));
    v.y = bfbits(__floats2bfloat162_rn(row[k0 + 8],  row[k0 + 9]));
    v.z = bfbits(__floats2bfloat162_rn(row[k0 + 16], row[k0 + 17]));
    v.w = bfbits(__floats2bfloat162_rn(row[k0 + 24], row[k0 + 25]));
    g_Wfrag[i] = v;
}

// ---- helpers ----
__device__ __forceinline__ void mma4(float* c, const uint4& a, uint32_t b0, uint32_t b1) {
    asm volatile("mma.sync.aligned.m16n8k16.row.col.f32.bf16.bf16.f32 "
        "{%0,%1,%2,%3}, {%4,%5,%6,%7}, {%8,%9}, {%0,%1,%2,%3};"
        : "+f"(c[0]), "+f"(c[1]), "+f"(c[2]), "+f"(c[3])
        : "r"(a.x), "r"(a.y), "r"(a.z), "r"(a.w), "r"(b0), "r"(b1));
}
__device__ __forceinline__ float tanh_fast(float x) {
    float y; asm("tanh.approx.f32 %0, %1;" : "=f"(y) : "f"(x)); return y;
}
__device__ __forceinline__ float fsig(float x) {
    return fmaf(0.5f, tanh_fast(0.5f * x), 0.5f);
}
__device__ __forceinline__ uint32_t packbf(float ev, float od) {
    uint32_t d; asm("cvt.rn.bf16x2.f32 %0, %1, %2;" : "=r"(d) : "f"(od), "f"(ev)); return d;
}
__device__ __forceinline__ float lo16f(uint32_t u) { return __uint_as_float(u << 16); }
__device__ __forceinline__ float hi16f(uint32_t u) { return __uint_as_float(u & 0xFFFF0000u); }

__device__ __forceinline__ void split_frag(const float* v, uint4& hi, uint4& lo) {
    hi.x = packbf(v[0], v[1]); lo.x = packbf(v[0] - lo16f(hi.x), v[1] - hi16f(hi.x));
    hi.y = packbf(v[2], v[3]); lo.y = packbf(v[2] - lo16f(hi.y), v[3] - hi16f(hi.y));
    hi.z = packbf(v[4], v[5]); lo.z = packbf(v[4] - lo16f(hi.z), v[5] - hi16f(hi.z));
    hi.w = packbf(v[6], v[7]); lo.w = packbf(v[6] - lo16f(hi.w), v[7] - hi16f(hi.w));
}
__device__ __forceinline__ void pack_hi(const float* v, uint4& hi) {
    hi.x = packbf(v[0], v[1]);
    hi.y = packbf(v[2], v[3]);
    hi.z = packbf(v[4], v[5]);
    hi.w = packbf(v[6], v[7]);
}

// ---- main kernel ----
__global__ void __launch_bounds__(THREADS, 1)
ode_mma_kernel(const float* __restrict__ times, const float* __restrict__ vals,
               const float* __restrict__ mask,  const float* __restrict__ b1,
               const float* __restrict__ b2,    const float* __restrict__ W_ih,
               const float* __restrict__ b_ih,  const float* __restrict__ b_hh,
               float* __restrict__ out)
{
    // hfrag: [kt][half(hi/lo)][lane]; t1frag: hi-only [kt][lane]
    __shared__ __align__(16) uint4 hfrag[8 * 2 * 32];   // 8 KB
    __shared__ __align__(16) uint4 t1frag[16 * 32];     // 8 KB
    __shared__ float obs_s[16], m_s[16];

    const int tid = threadIdx.x, w = tid >> 5, lane = tid & 31;
    const int g = lane >> 2, t = lane & 3;
    const int f0 = blockIdx.x * MF;

    // ---- loop-invariant per-lane preloads ----
    float b1v[8];
    #pragma unroll
    for (int nt = 0; nt < 4; ++nt) {
        const int j = 32 * w + nt * 8 + 2 * t;
        b1v[nt * 2]     = __ldg(b1 + j);
        b1v[nt * 2 + 1] = __ldg(b1 + j + 1);
    }
    float b2v[8], bcr[8], bcz[8], bhn[8], bin[8], wir[8], wiz[8], win[8];
    #pragma unroll
    for (int q = 0; q < 8; ++q) {
        const int k = 16 * w + (q >> 2) * 8 + 2 * t + (q & 1);
        b2v[q] = __ldg(b2 + k);
        bcr[q] = __ldg(b_hh + k)       + __ldg(b_ih + k);
        bcz[q] = __ldg(b_hh + 128 + k) + __ldg(b_ih + 128 + k);
        bhn[q] = __ldg(b_hh + 256 + k);
        bin[q] = __ldg(b_ih + 256 + k);
        wir[q] = __ldg(W_ih + k);
        wiz[q] = __ldg(W_ih + 128 + k);
        win[q] = __ldg(W_ih + 256 + k);
    }

    float h[8];
    #pragma unroll
    for (int q = 0; q < 8; ++q) h[q] = 0.0f;
    {
        uint4 hi, lo;
        split_frag(h, hi, lo);
        hfrag[(w * 2 + 0) * 32 + lane] = hi;
        hfrag[(w * 2 + 1) * 32 + lane] = lo;
    }
    __syncthreads();

    for (int i = 0; i < T_STEPS; ++i) {
        const int rowi = T_STEPS - 1 - i;
        float dt = 0.0f;
        if (i > 0) dt = __ldg(times + rowi + 1) - __ldg(times + rowi);

        if (tid < 16)      obs_s[tid]    = __ldg(vals + (long)rowi * F_FEAT + f0 + tid);
        else if (tid < 32) m_s[tid - 16] = __ldg(mask + (long)rowi * F_FEAT + f0 + tid - 16);

        if (dt > 0.0f) {
            // ---- P1: C(16x256) = H_hi(16x128) @ W1^T ; warp w: n-cols [32w,32w+32) ----
            float c[4][4];
            #pragma unroll
            for (int nt = 0; nt < 4; ++nt)
                #pragma unroll
                for (int cc = 0; cc < 4; ++cc) c[nt][cc] = 0.0f;
            uint4 bwA[4], bwB[4];
            #pragma unroll
            for (int nt = 0; nt < 4; ++nt)
                bwA[nt] = __ldg(&g_Wfrag[W1_BASE + (((4 * w + nt) * 4 + 0) * 32 + lane)]);
            #pragma unroll
            for (int ktp = 0; ktp < 4; ++ktp) {
                uint4* cur = (ktp & 1) ? bwB : bwA;
                uint4* nxt = (ktp & 1) ? bwA : bwB;
                if (ktp < 3) {
                    #pragma unroll
                    for (int nt = 0; nt < 4; ++nt)
                        nxt[nt] = __ldg(&g_Wfrag[W1_BASE + (((4 * w + nt) * 4 + ktp + 1) * 32 + lane)]);
                }
                const uint4 ah0 = hfrag[((2 * ktp)     * 2 + 0) * 32 + lane];
                const uint4 ah1 = hfrag[((2 * ktp + 1) * 2 + 0) * 32 + lane];
                #pragma unroll
                for (int nt = 0; nt < 4; ++nt) {
                    mma4(c[nt], ah0, cur[nt].x, cur[nt].y);
                    mma4(c[nt], ah1, cur[nt].z, cur[nt].w);
                }
            }
            // epilogue: tanh(+b1) -> T1 hi-only A-frags (ktiles 2w, 2w+1)
            float v[16];
            #pragma unroll
            for (int nt = 0; nt < 4; ++nt)
                #pragma unroll
                for (int cc = 0; cc < 4; ++cc)
                    v[nt * 4 + cc] = tanh_fast(c[nt][cc] + b1v[nt * 2 + (cc & 1)]);
            #pragma unroll
            for (int kt2 = 0; kt2 < 2; ++kt2) {
                uint4 hi;
                pack_hi(v + kt2 * 8, hi);
                t1frag[(2 * w + kt2) * 32 + lane] = hi;
            }
            // prefetch P2 ktp0 weights across the barrier
            uint4 dwA[2], dwB[2];
            #pragma unroll
            for (int nt = 0; nt < 2; ++nt)
                dwA[nt] = __ldg(&g_Wfrag[W2_BASE + (((2 * w + nt) * 8 + 0) * 32 + lane)]);
            __syncthreads();

            // ---- P2: C(16x128) = T1_hi(16x256) @ W2^T ; warp w: n-cols [16w,16w+16) ----
            float d[2][4];
            #pragma unroll
            for (int nt = 0; nt < 2; ++nt)
                #pragma unroll
                for (int cc = 0; cc < 4; ++cc) d[nt][cc] = 0.0f;
            #pragma unroll
            for (int ktp = 0; ktp < 8; ++ktp) {
                uint4* cur = (ktp & 1) ? dwB : dwA;
                uint4* nxt = (ktp & 1) ? dwA : dwB;
                if (ktp < 7) {
                    #pragma unroll
                    for (int nt = 0; nt < 2; ++nt)
                        nxt[nt] = __ldg(&g_Wfrag[W2_BASE + (((2 * w + nt) * 8 + ktp + 1) * 32 + lane)]);
                }
                const uint4 ah0 = t1frag[(2 * ktp)     * 32 + lane];
                const uint4 ah1 = t1frag[(2 * ktp + 1) * 32 + lane];
                #pragma unroll
                for (int nt = 0; nt < 2; ++nt) {
                    mma4(d[nt], ah0, cur[nt].x, cur[nt].y);
                    mma4(d[nt], ah1, cur[nt].z, cur[nt].w);
                }
            }
            // epilogue: h += dt * (dH + b2); refresh h frag (hi+lo)
            #pragma unroll
            for (int q = 0; q < 8; ++q)
                h[q] = fmaf(dt, d[q >> 2][q & 3] + b2v[q], h[q]);
            {
                uint4 hi, lo;
                split_frag(h, hi, lo);
                hfrag[(w * 2 + 0) * 32 + lane] = hi;
                hfrag[(w * 2 + 1) * 32 + lane] = lo;
            }
        }
        // prefetch P3 ktp0 weights across the barrier
        uint4 ewA[6], ewB[6];
        #pragma unroll
        for (int j6 = 0; j6 < 6; ++j6)
            ewA[j6] = __ldg(&g_Wfrag[WH_BASE + ((((j6 >> 1) * 16 + 2 * w + (j6 & 1)) * 4 + 0) * 32 + lane)]);
        __syncthreads();

        // ---- P3: GH(16x384) = H(hi+lo) @ Whh^T ; warp w: cols 16w..16w+16 per third ----
        float e[6][4];
        #pragma unroll
        for (int nt = 0; nt < 6; ++nt)
            #pragma unroll
            for (int cc = 0; cc < 4; ++cc) e[nt][cc] = 0.0f;
        #pragma unroll
        for (int ktp = 0; ktp < 4; ++ktp) {
            uint4* cur = (ktp & 1) ? ewB : ewA;
            uint4* nxt = (ktp & 1) ? ewA : ewB;
            if (ktp < 3) {
                #pragma unroll
                for (int j6 = 0; j6 < 6; ++j6)
                    nxt[j6] = __ldg(&g_Wfrag[WH_BASE + ((((j6 >> 1) * 16 + 2 * w + (j6 & 1)) * 4 + ktp + 1) * 32 + lane)]);
            }
            const uint4 ah0 = hfrag[((2 * ktp)     * 2 + 0) * 32 + lane];
            const uint4 al0 = hfrag[((2 * ktp)     * 2 + 1) * 32 + lane];
            const uint4 ah1 = hfrag[((2 * ktp + 1) * 2 + 0) * 32 + lane];
            const uint4 al1 = hfrag[((2 * ktp + 1) * 2 + 1) * 32 + lane];
            #pragma unroll
            for (int j6 = 0; j6 < 6; ++j6) {
                float* acc = e[j6];
                mma4(acc, ah0, cur[j6].x, cur[j6].y);
                mma4(acc, al0, cur[j6].x, cur[j6].y);
                mma4(acc, ah1, cur[j6].z, cur[j6].w);
                mma4(acc, al1, cur[j6].z, cur[j6].w);
            }
        }
        // epilogue: GRU + mask mix, in-place on h regs
        {
            const float ob0 = obs_s[g], ob1 = obs_s[g + 8];
            const float mm0 = m_s[g],   mm1 = m_s[g + 8];
            #pragma unroll
            for (int q = 0; q < 8; ++q) {
                const int tile = q >> 2, cc = q & 3;
                const float ob = (cc & 2) ? ob1 : ob0;
                const float mm = (cc & 2) ? mm1 : mm0;
                const float r = fsig(fmaf(ob, wir[q], bcr[q]) + e[tile][cc]);
                const float z = fsig(fmaf(ob, wiz[q], bcz[q]) + e[2 + tile][cc]);
                const float n = tanh_fast(fmaf(ob, win[q], bin[q]) + r * (e[4 + tile][cc] + bhn[q]));
                const float hv = h[q];
                const float hc = fmaf(z, hv - n, n);
                h[q] = fmaf(mm, hc - hv, hv);
            }
        }
        {
            uint4 hi, lo;
            split_frag(h, hi, lo);
            hfrag[(w * 2 + 0) * 32 + lane] = hi;
            hfrag[(w * 2 + 1) * 32 + lane] = lo;
        }
        __syncthreads();
    }

    // ---- output: decode fragment layout ----
    #pragma unroll
    for (int q = 0; q < 8; ++q) {
        const int rowf = g + ((q & 3) >> 1) * 8;
        const int k    = 16 * w + (q >> 2) * 8 + 2 * t + (q & 1);
        out[(long)(f0 + rowf) * 128 + k] = h[q];
    }
}

extern "C" void kernel_launch(void* const* d_in, const int* in_sizes, int n_in,
                              void* d_out, int out_size)
{
    (void)in_sizes; (void)n_in; (void)out_size;
    const float* times = (const float*)d_in[0];
    const float* vals  = (const float*)d_in[1];
    const float* mask  = (const float*)d_in[2];
    const float* W1    = (const float*)d_in[3];
    const float* b1    = (const float*)d_in[4];
    const float* W2    = (const float*)d_in[5];
    const float* b2    = (const float*)d_in[6];
    const float* W_ih  = (const float*)d_in[7];
    const float* b_ih  = (const float*)d_in[8];
    const float* W_hh  = (const float*)d_in[9];
    const float* b_hh  = (const float*)d_in[10];
    float* out = (float*)d_out;

    repack_kernel<<<56, 256>>>(W1, W2, W_hh);
    ode_mma_kernel<<<NCTA, THREADS>>>(times, vals, mask, b1, b2,
                                      W_ih, b_ih, b_hh, out);
}